// round 16
// baseline (speedup 1.0000x reference)
#include <cuda_runtime.h>
#include <cuda_bf16.h>
#include <cstdint>
#include <math.h>

// Problem dims (fixed per reference)
#define NROWS 16384
#define IND   512
#define HIDD  256
#define OD    128
#define NB    (NROWS / 128)

// Blocked XOR-swizzled tile formats (validated R10/R14):
//  A-style block: 128 rows x 128 bytes; B-style block: 64 rows x 256 bytes
//  off = r*ROWB + (((b>>4) ^ (r&7))<<4) + (b&15)

// Scratch (device globals; no allocations allowed)
__device__ __nv_bfloat16 g_xb [NROWS * IND];    // x blocked A-blocks
__device__ __nv_bfloat16 g_w1b[IND * HIDD];     // W1 blocked B-blocks
__device__ __nv_bfloat16 g_w2b[HIDD * OD];      // W2 blocked B-blocks
__device__ __nv_bfloat16 g_h1b[NROWS * HIDD];   // h1 blocked A-blocks
__device__ float         g_h  [NROWS * OD];     // fp32 h (epilogue)
// bf16 h swizzled: 128 blocks of 32KB (256B rows)
__device__ __nv_bfloat16 g_hb [NROWS * OD];
// bf16 h^T HALF blocks: per kb, rows d=64..127 (64 rows x 256B = 16KB)
__device__ __nv_bfloat16 g_hbT2[(OD / 2) * NROWS];

// ===========================================================================
// PTX helpers
// ===========================================================================
__device__ __forceinline__ uint32_t smem_to_u32(const void* p) {
    uint32_t a;
    asm("{ .reg .u64 t; cvta.to.shared.u64 t, %1; cvt.u32.u64 %0, t; }"
        : "=r"(a) : "l"(p));
    return a;
}

__device__ __forceinline__ void bulk_cp(uint32_t dst, const void* src,
                                        uint32_t bytes, uint32_t mbar) {
    asm volatile(
        "cp.async.bulk.shared::cluster.global.mbarrier::complete_tx::bytes "
        "[%0], [%1], %2, [%3];"
        :: "r"(dst), "l"(src), "r"(bytes), "r"(mbar) : "memory");
}

#define MBARRIER_INIT(mbar, cnt) \
    asm volatile("mbarrier.init.shared.b64 [%0], %1;" \
        :: "r"((uint32_t)(mbar)), "r"((uint32_t)(cnt)) : "memory")
#define MBARRIER_EXPECT_TX(mbar, tx) \
    asm volatile("mbarrier.arrive.expect_tx.shared.b64 _, [%0], %1;" \
        :: "r"((uint32_t)(mbar)), "r"((uint32_t)(tx)) : "memory")
#define MBARRIER_WAIT_PARITY(mbar, parity) do {                                   \
    uint32_t _m = (uint32_t)(mbar);                                               \
    uint32_t _p = (uint32_t)(parity);                                             \
    uint32_t _done;                                                               \
    asm volatile(                                                                 \
        "{\n\t.reg .pred p;\n\t"                                                  \
        "mbarrier.try_wait.parity.acquire.cta.shared::cta.b64 p, [%1], %2;\n\t"   \
        "selp.b32 %0, 1, 0, p;\n\t}"                                              \
        : "=r"(_done) : "r"(_m), "r"(_p) : "memory");                             \
    if (!_done) {                                                                 \
        asm volatile(                                                             \
            "{\n\t.reg .pred P1;\n\t"                                             \
            "WAIT_LOOP_%=:\n\t"                                                   \
            "mbarrier.try_wait.parity.acquire.cta.shared::cta.b64 P1, [%0], %1, 0x989680;\n\t" \
            "@P1 bra.uni WAIT_DONE_%=;\n\t"                                       \
            "bra.uni WAIT_LOOP_%=;\n\t"                                           \
            "WAIT_DONE_%=:\n\t}"                                                  \
            :: "r"(_m), "r"(_p) : "memory");                                      \
    }                                                                             \
} while (0)

__device__ __forceinline__ void ldsm_x4(uint32_t* r, uint32_t addr) {
    asm volatile("ldmatrix.sync.aligned.m8n8.x4.shared.b16 {%0,%1,%2,%3}, [%4];"
                 : "=r"(r[0]), "=r"(r[1]), "=r"(r[2]), "=r"(r[3]) : "r"(addr));
}
__device__ __forceinline__ void ldsm_x4_t(uint32_t* r, uint32_t addr) {
    asm volatile("ldmatrix.sync.aligned.m8n8.x4.trans.shared.b16 {%0,%1,%2,%3}, [%4];"
                 : "=r"(r[0]), "=r"(r[1]), "=r"(r[2]), "=r"(r[3]) : "r"(addr));
}
__device__ __forceinline__ uint32_t movm(uint32_t a) {
    uint32_t d;
    asm("movmatrix.sync.aligned.m8n8.trans.b16 %0, %1;" : "=r"(d) : "r"(a));
    return d;
}

__device__ __forceinline__ void mma16816(float* c, const uint32_t* a,
                                         const uint32_t b0, const uint32_t b1) {
    asm volatile(
        "mma.sync.aligned.m16n8k16.row.col.f32.bf16.bf16.f32 "
        "{%0,%1,%2,%3}, {%4,%5,%6,%7}, {%8,%9}, {%0,%1,%2,%3};"
        : "+f"(c[0]), "+f"(c[1]), "+f"(c[2]), "+f"(c[3])
        : "r"(a[0]), "r"(a[1]), "r"(a[2]), "r"(a[3]), "r"(b0), "r"(b1));
}

__device__ __forceinline__ uint32_t pack_bf16x2(float hi, float lo) {
    uint32_t d;
    asm("cvt.rn.bf16x2.f32 %0, %1, %2;" : "=r"(d) : "f"(hi), "f"(lo));
    return d;
}
__device__ __forceinline__ uint32_t hmul2(uint32_t a, uint32_t b) {
    uint32_t d;
    asm("mul.rn.bf16x2 %0, %1, %2;" : "=r"(d) : "r"(a), "r"(b));
    return d;
}
__device__ __forceinline__ float ex2f(float x) {
    float d;
    asm("ex2.approx.f32 %0, %1;" : "=f"(d) : "f"(x));
    return d;
}
#define L2E_BF16X2 0x3FB93FB9u   // bf16x2 {log2(e), log2(e)}

// ===========================================================================
// Conversions into blocked swizzled layouts (unchanged from R14/R15)
// ===========================================================================
__global__ __launch_bounds__(256) void cvt_x_blocked(
    const float* __restrict__ x, __nv_bfloat16* __restrict__ xb)
{
    int idx = blockIdx.x * 256 + threadIdx.x;
    int r = idx >> 6;
    int cc = idx & 63;
    const float4* src = (const float4*)(x + (size_t)r * IND + cc * 8);
    float4 v0 = src[0], v1 = src[1];
    uint4 o = make_uint4(pack_bf16x2(v0.y, v0.x), pack_bf16x2(v0.w, v0.z),
                         pack_bf16x2(v1.y, v1.x), pack_bf16x2(v1.w, v1.z));
    uint32_t blk = (uint32_t)((r >> 7) * 8 + (cc >> 3));
    uint32_t off = blk * 16384u + (uint32_t)(r & 127) * 128u
                 + (uint32_t)((((cc & 7) ^ (r & 7)) << 4));
    *(uint4*)((char*)xb + off) = o;
}

template<int K, int NCOLS>
__global__ __launch_bounds__(256) void cvt_w_blocked(
    const float* __restrict__ w, __nv_bfloat16* __restrict__ wb)
{
    int idx = blockIdx.x * 256 + threadIdx.x;
    int cpr = NCOLS / 8;
    int k = idx / cpr;
    int cc = idx % cpr;
    int n0 = cc * 8;
    const float4* src = (const float4*)(w + (size_t)k * NCOLS + n0);
    float4 v0 = src[0], v1 = src[1];
    uint4 o = make_uint4(pack_bf16x2(v0.y, v0.x), pack_bf16x2(v0.w, v0.z),
                         pack_bf16x2(v1.y, v1.x), pack_bf16x2(v1.w, v1.z));
    uint32_t blk = (uint32_t)((k >> 6) * (NCOLS / 128) + (n0 >> 7));
    uint32_t ch  = (uint32_t)((n0 & 127) >> 3);
    uint32_t off = blk * 16384u + (uint32_t)(k & 63) * 256u
                 + ((ch ^ (uint32_t)(k & 7)) << 4);
    *(uint4*)((char*)wb + off) = o;
}

// ===========================================================================
// Half transpose: g_h fp32 -> g_hbT2 (per kb: rows d=64..127, [64][128n],
// 256B swizzled rows). Values are cvt.rn of same fp32 as g_hb -> bit-identical.
// ===========================================================================
__global__ __launch_bounds__(256) void transpose_half_kernel(
    const float* __restrict__ h, __nv_bfloat16* __restrict__ hbT2)
{
    __shared__ __nv_bfloat16 tile[128][65];   // [n][d-64]
    const int kb = blockIdx.x;
    const int tid = threadIdx.x;

    for (int idx = tid; idx < 128 * 64; idx += 256) {
        int n = idx >> 6, d = 64 + (idx & 63);
        tile[n][d - 64] = __float2bfloat16(h[(size_t)(kb * 128 + n) * OD + d]);
    }
    __syncthreads();

    char* dst = (char*)hbT2 + (size_t)kb * 16384;
    for (int idx = tid; idx < 64 * 32; idx += 256) {
        int dd = idx >> 5;
        int n = (idx & 31) * 4;
        uint32_t lo = pack_bf16x2(__bfloat162float(tile[n + 1][dd]),
                                  __bfloat162float(tile[n + 0][dd]));
        uint32_t hi = pack_bf16x2(__bfloat162float(tile[n + 3][dd]),
                                  __bfloat162float(tile[n + 2][dd]));
        uint32_t chunk = (uint32_t)(n >> 3);
        uint32_t off = (uint32_t)dd * 256u
            + (((chunk ^ (uint32_t)(dd & 7)) << 4) | (uint32_t)((n * 2) & 15));
        *(uint2*)(dst + off) = make_uint2(lo, hi);
    }
}

// ===========================================================================
// bf16 HMMA GEMM with bulk-copied blocked operands (R15, frozen)
// ===========================================================================
#define GT_A 16384
#define GT_B 16384
#define GT_STG (GT_A + GT_B)
#define GEMM_SMEM (3 * GT_STG + 64)

template<int KDIM, int NGLOB, bool LEAKY, bool WRITE_F32, bool H1B_OUT, bool SWZ_CB>
__global__ __launch_bounds__(256, 2) void hgemm_bulk_kernel(
    const __nv_bfloat16* __restrict__ A, const __nv_bfloat16* __restrict__ B,
    const float* __restrict__ bias, float* __restrict__ C,
    __nv_bfloat16* __restrict__ Cb)
{
    extern __shared__ char smem[];
    const uint32_t sb = smem_to_u32(smem);
    const uint32_t mb = sb + 3 * GT_STG;
    const int tid = threadIdx.x;
    const int wid = tid >> 5, lane = tid & 31;
    const int m0 = blockIdx.y * 128, n0 = blockIdx.x * 128;
    const char* Abase = (const char*)A;
    const char* Bbase = (const char*)B;
    constexpr int NC = KDIM / 64;

    if (tid == 0) {
        MBARRIER_INIT(mb, 1);
        MBARRIER_INIT(mb + 8, 1);
        MBARRIER_INIT(mb + 16, 1);
    }
    __syncthreads();

    auto kick = [&](int stg, int ck) {
        const uint32_t m_ = mb + 8u * (uint32_t)stg;
        const uint32_t d_ = sb + (uint32_t)stg * GT_STG;
        MBARRIER_EXPECT_TX(m_, GT_STG);
        bulk_cp(d_, Abase + ((size_t)(m0 >> 7) * NC + ck) * 16384, GT_A, m_);
        bulk_cp(d_ + GT_A,
                Bbase + ((size_t)ck * (NGLOB / 128) + (n0 >> 7)) * 16384,
                GT_B, m_);
    };
    if (tid == 0) {
        kick(0, 0);
        if (NC > 1) kick(1, 1);
        if (NC > 2) kick(2, 2);
    }

    float acc[16][4];
    #pragma unroll
    for (int i = 0; i < 16; i++)
        #pragma unroll
        for (int j = 0; j < 4; j++) acc[i][j] = 0.f;

    const int brow = lane & 15;
    const int hc = lane >> 4;
    const int xr = lane & 7;
    const int vrow = ((lane >> 4) << 3) + (lane & 7);
    const int vhc = (lane >> 3) & 1;

    int st = 0, ph = 0;
    for (int ck = 0; ck < NC; ck++) {
        MBARRIER_WAIT_PARITY(mb + 8u * (uint32_t)st, ph);

        const uint32_t cA = sb + (uint32_t)st * GT_STG;
        const uint32_t cB = cA + GT_A;

        uint32_t af[4][4];
        const uint32_t ab = cA + (uint32_t)(wid * 16 + brow) * 128u;
        #pragma unroll
        for (int kt = 0; kt < 4; kt++)
            ldsm_x4(af[kt], ab + (uint32_t)(((kt * 2 + hc) ^ xr) << 4));

        #pragma unroll
        for (int kt = 0; kt < 4; kt++) {
            const uint32_t rbrow = cB + (uint32_t)(kt * 16 + vrow) * 256u;
            #pragma unroll
            for (int jp = 0; jp < 8; jp++) {
                uint32_t r[4];
                ldsm_x4_t(r, rbrow + (uint32_t)(((jp * 2 + vhc) ^ xr) << 4));
                mma16816(acc[2 * jp],     af[kt], r[0], r[2]);
                mma16816(acc[2 * jp + 1], af[kt], r[1], r[3]);
            }
        }

        if (ck + 3 < NC) {
            __syncthreads();
            if (tid == 0) kick(st, ck + 3);
        }

        if (++st == 3) { st = 0; ph ^= 1; }
    }

    const int g = lane >> 2, t = lane & 3;
    const int row_lo = m0 + wid * 16 + g;
    const int row_hi = row_lo + 8;
    #pragma unroll
    for (int nt = 0; nt < 16; nt++) {
        const int col = n0 + nt * 8 + 2 * t;
        const float bb0 = bias[col], bb1 = bias[col + 1];
        float v0 = acc[nt][0] + bb0, v1 = acc[nt][1] + bb1;
        float v2 = acc[nt][2] + bb0, v3 = acc[nt][3] + bb1;
        if (LEAKY) {
            v0 = v0 >= 0.f ? v0 : 0.01f * v0;
            v1 = v1 >= 0.f ? v1 : 0.01f * v1;
            v2 = v2 >= 0.f ? v2 : 0.01f * v2;
            v3 = v3 >= 0.f ? v3 : 0.01f * v3;
        }
        if (WRITE_F32) {
            *(float2*)(C + (size_t)row_lo * NGLOB + col) = make_float2(v0, v1);
            *(float2*)(C + (size_t)row_hi * NGLOB + col) = make_float2(v2, v3);
        }
        if (H1B_OUT) {
            const uint32_t ck2 = (uint32_t)(col >> 6);
            const uint32_t ch  = (uint32_t)((col & 63) >> 3);
            const uint32_t inb = (uint32_t)((col * 2) & 15);
            const uint32_t b_lo = ((uint32_t)(row_lo >> 7) * (NGLOB / 64) + ck2) * 16384u
                + (uint32_t)(row_lo & 127) * 128u
                + (((ch ^ (uint32_t)(row_lo & 7)) << 4) | inb);
            const uint32_t b_hi = ((uint32_t)(row_hi >> 7) * (NGLOB / 64) + ck2) * 16384u
                + (uint32_t)(row_hi & 127) * 128u
                + (((ch ^ (uint32_t)(row_hi & 7)) << 4) | inb);
            *(uint32_t*)((char*)Cb + b_lo) = pack_bf16x2(v1, v0);
            *(uint32_t*)((char*)Cb + b_hi) = pack_bf16x2(v3, v2);
        }
        if (SWZ_CB) {
            const uint32_t chunk = (uint32_t)(col >> 3);
            const uint32_t inb   = (uint32_t)((col * 2) & 15);
            const uint32_t off_lo = ((uint32_t)(row_lo >> 7)) * 32768u
                + (uint32_t)(row_lo & 127) * 256u
                + (((chunk ^ (uint32_t)(row_lo & 7)) << 4) | inb);
            const uint32_t off_hi = ((uint32_t)(row_hi >> 7)) * 32768u
                + (uint32_t)(row_hi & 127) * 256u
                + (((chunk ^ (uint32_t)(row_hi & 7)) << 4) | inb);
            *(uint32_t*)((char*)Cb + off_lo) = pack_bf16x2(v1, v0);
            *(uint32_t*)((char*)Cb + off_hi) = pack_bf16x2(v3, v2);
        }
    }
}

// ===========================================================================
// HMMA flash similarity kernel — R16 hybrid PV:
//   dk 0..3: B-frags via movmatrix (tensor pipe)
//   dk 4..7: B-frags via non-trans ldsm on half V^T tile (shared pipe)
//   Tensor/iter 6144 -> 5120; crossbar 2048 -> 3072 (still below tensor).
//   3-stage pipeline, K 32KB + VT 16KB per stage.
// ===========================================================================
#define TILE_K 32768
#define TILE_V 16384
#define TILE_S (TILE_K + TILE_V)
#define FLASH_SMEM (3 * TILE_S + 64)   // 147520

__global__ __launch_bounds__(256, 1)
void flash_hmma_kernel(const __nv_bfloat16* __restrict__ hbs,   // swizzled K
                       const __nv_bfloat16* __restrict__ hbT2s, // half V^T
                       const float* __restrict__ h,
                       const float* __restrict__ alpha,
                       const float* __restrict__ beta,
                       float* __restrict__ out)
{
    extern __shared__ char smem[];
    const uint32_t sbase = smem_to_u32(smem);
    const uint32_t mQ = sbase + 3 * TILE_S;   // key-stage mb[s] at mQ+8+8s
    const int tid = threadIdx.x;
    const int wid = tid >> 5, lane = tid & 31;
    const int r0 = blockIdx.x * 128;
    const char* kbase = (const char*)hbs;
    const char* vbase = (const char*)hbT2s;

    if (tid == 0) {
        MBARRIER_INIT(mQ, 1);
        MBARRIER_INIT(mQ + 8, 1);
        MBARRIER_INIT(mQ + 16, 1);
        MBARRIER_INIT(mQ + 24, 1);
    }
    __syncthreads();

    if (tid == 0) {
        MBARRIER_EXPECT_TX(mQ, TILE_K);
        bulk_cp(sbase, kbase + (size_t)blockIdx.x * TILE_K, TILE_K, mQ);
    }

    const int brow = lane & 15;
    const int hc = lane >> 4;
    const int xr = lane & 7;
    uint32_t choff[8];
    #pragma unroll
    for (int dk = 0; dk < 8; dk++)
        choff[dk] = (uint32_t)(((dk * 2 + hc) ^ xr) << 4);

    MBARRIER_WAIT_PARITY(mQ, 0);

    uint32_t qf[8][4];
    {
        const uint32_t qb = sbase + (uint32_t)(wid * 16 + brow) * 256u;
        #pragma unroll
        for (int kt = 0; kt < 8; kt++) {
            ldsm_x4(qf[kt], qb + choff[kt]);
            #pragma unroll
            for (int i = 0; i < 4; i++)
                qf[kt][i] = hmul2(qf[kt][i], L2E_BF16X2);  // fold log2(e)
        }
    }
    __syncthreads();   // all threads done reading Q from stage0 K-slot

    // Kick key-blocks 0..1 into stages 0..1 (K + half-VT each)
    if (tid == 0) {
        MBARRIER_EXPECT_TX(mQ + 8, TILE_S);
        bulk_cp(sbase, kbase, TILE_K, mQ + 8);
        bulk_cp(sbase + TILE_K, vbase, TILE_V, mQ + 8);
        MBARRIER_EXPECT_TX(mQ + 16, TILE_S);
        bulk_cp(sbase + TILE_S, kbase + TILE_K, TILE_K, mQ + 16);
        bulk_cp(sbase + TILE_S + TILE_K, vbase + TILE_V, TILE_V, mQ + 16);
    }

    float oacc[16][4];
    #pragma unroll
    for (int i = 0; i < 16; i++)
        #pragma unroll
        for (int j = 0; j < 4; j++) oacc[i][j] = 0.f;
    float l0 = 0.f, l1 = 0.f;

    int st = 0, ph = 0;
    for (int kb = 0; kb < NB; kb++) {
        MBARRIER_WAIT_PARITY(mQ + 8 + 8 * (uint32_t)st, ph);
        __syncthreads();   // iter kb-1 done -> stage (st+2)%3 is free
        if (tid == 0 && kb + 2 < NB) {
            int pst = st + 2; if (pst >= 3) pst -= 3;
            const uint32_t mm = mQ + 8 + 8 * (uint32_t)pst;
            const uint32_t db = sbase + (uint32_t)pst * TILE_S;
            MBARRIER_EXPECT_TX(mm, TILE_S);
            bulk_cp(db, kbase + (size_t)(kb + 2) * TILE_K, TILE_K, mm);
            bulk_cp(db + TILE_K, vbase + (size_t)(kb + 2) * TILE_V, TILE_V, mm);
        }

        const uint32_t cur  = sbase + (uint32_t)st * TILE_S;
        const uint32_t curV = cur + TILE_K;
        const uint32_t vbrow = curV + (uint32_t)brow * 256u;

        #pragma unroll
        for (int nbk = 0; nbk < 8; nbk++) {
            uint32_t r[8][4];
            const uint32_t rb = cur + (uint32_t)(nbk * 16 + brow) * 256u;
            #pragma unroll
            for (int dk = 0; dk < 8; dk++) ldsm_x4(r[dk], rb + choff[dk]);

            float s0[4] = {0.f, 0.f, 0.f, 0.f};
            float s1[4] = {0.f, 0.f, 0.f, 0.f};
            #pragma unroll
            for (int dk = 0; dk < 8; dk++) {
                mma16816(s0, qf[dk], r[dk][0], r[dk][2]);
                mma16816(s1, qf[dk], r[dk][1], r[dk][3]);
            }

            float p00 = s0[0] > 0.f ? ex2f(s0[0]) : 0.f;
            float p01 = s0[1] > 0.f ? ex2f(s0[1]) : 0.f;
            float p02 = s0[2] > 0.f ? ex2f(s0[2]) : 0.f;
            float p03 = s0[3] > 0.f ? ex2f(s0[3]) : 0.f;
            float p10 = s1[0] > 0.f ? ex2f(s1[0]) : 0.f;
            float p11 = s1[1] > 0.f ? ex2f(s1[1]) : 0.f;
            float p12 = s1[2] > 0.f ? ex2f(s1[2]) : 0.f;
            float p13 = s1[3] > 0.f ? ex2f(s1[3]) : 0.f;
            l0 += (p00 + p01) + (p10 + p11);
            l1 += (p02 + p03) + (p12 + p13);
            uint32_t af[4] = { pack_bf16x2(p01, p00), pack_bf16x2(p03, p02),
                               pack_bf16x2(p11, p10), pack_bf16x2(p13, p12) };

            // PV hybrid: dk 0..3 via movm (tensor), dk 4..7 via ldsm on VT
            const uint32_t vch = (uint32_t)(((nbk * 2 + hc) ^ xr) << 4);
            #pragma unroll
            for (int dk = 0; dk < 4; dk++) {
                mma16816(oacc[2 * dk],     af, movm(r[dk][0]), movm(r[dk][1]));
                mma16816(oacc[2 * dk + 1], af, movm(r[dk][2]), movm(r[dk][3]));
            }
            #pragma unroll
            for (int dk = 4; dk < 8; dk++) {
                uint32_t rv[4];
                ldsm_x4(rv, vbrow + (uint32_t)(dk - 4) * 4096u + vch);
                mma16816(oacc[2 * dk],     af, rv[0], rv[2]);
                mma16816(oacc[2 * dk + 1], af, rv[1], rv[3]);
            }
        }

        if (++st == 3) { st = 0; ph ^= 1; }
    }

    l0 += __shfl_xor_sync(0xffffffffu, l0, 1);
    l0 += __shfl_xor_sync(0xffffffffu, l0, 2);
    l1 += __shfl_xor_sync(0xffffffffu, l1, 1);
    l1 += __shfl_xor_sync(0xffffffffu, l1, 2);

    const float a_ = alpha[0], b_ = beta[0];
    const float s0_ = a_ / l0, s1_ = a_ / l1;
    const int g = lane >> 2, t = lane & 3;
    const int row_lo = r0 + wid * 16 + g;
    const int row_hi = row_lo + 8;

    float mx0 = -INFINITY, mx1 = -INFINITY;
    #pragma unroll
    for (int nt = 0; nt < 16; nt++) {
        const int col = nt * 8 + 2 * t;
        float2 hlo = *(const float2*)(h + (size_t)row_lo * OD + col);
        float2 hhi = *(const float2*)(h + (size_t)row_hi * OD + col);
        float v0 = s0_ * oacc[nt][0] + b_ * hlo.x;
        float v1 = s0_ * oacc[nt][1] + b_ * hlo.y;
        float v2 = s1_ * oacc[nt][2] + b_ * hhi.x;
        float v3 = s1_ * oacc[nt][3] + b_ * hhi.y;
        oacc[nt][0] = v0; oacc[nt][1] = v1;
        oacc[nt][2] = v2; oacc[nt][3] = v3;
        mx0 = fmaxf(mx0, fmaxf(v0, v1));
        mx1 = fmaxf(mx1, fmaxf(v2, v3));
    }
    mx0 = fmaxf(mx0, __shfl_xor_sync(0xffffffffu, mx0, 1));
    mx0 = fmaxf(mx0, __shfl_xor_sync(0xffffffffu, mx0, 2));
    mx1 = fmaxf(mx1, __shfl_xor_sync(0xffffffffu, mx1, 1));
    mx1 = fmaxf(mx1, __shfl_xor_sync(0xffffffffu, mx1, 2));

    float se0 = 0.f, se1 = 0.f;
    #pragma unroll
    for (int nt = 0; nt < 16; nt++) {
        se0 += __expf(oacc[nt][0] - mx0) + __expf(oacc[nt][1] - mx0);
        se1 += __expf(oacc[nt][2] - mx1) + __expf(oacc[nt][3] - mx1);
    }
    se0 += __shfl_xor_sync(0xffffffffu, se0, 1);
    se0 += __shfl_xor_sync(0xffffffffu, se0, 2);
    se1 += __shfl_xor_sync(0xffffffffu, se1, 1);
    se1 += __shfl_xor_sync(0xffffffffu, se1, 2);
    const float lse0 = mx0 + logf(se0);
    const float lse1 = mx1 + logf(se1);

    #pragma unroll
    for (int nt = 0; nt < 16; nt++) {
        const int col = nt * 8 + 2 * t;
        *(float2*)(out + (size_t)row_lo * OD + col) =
            make_float2(oacc[nt][0] - lse0, oacc[nt][1] - lse0);
        *(float2*)(out + (size_t)row_hi * OD + col) =
            make_float2(oacc[nt][2] - lse1, oacc[nt][3] - lse1);
    }
}

// ===========================================================================
// Launch. Inputs: 0:x 1:g 2:W1 3:b1 4:W2 5:b2 6:alpha 7:beta
// ===========================================================================
extern "C" void kernel_launch(void* const* d_in, const int* in_sizes, int n_in,
                              void* d_out, int out_size)
{
    (void)in_sizes; (void)n_in; (void)out_size;
    const float* x     = (const float*)d_in[0];
    const float* W1    = (const float*)d_in[2];
    const float* b1    = (const float*)d_in[3];
    const float* W2    = (const float*)d_in[4];
    const float* b2    = (const float*)d_in[5];
    const float* alpha = (const float*)d_in[6];
    const float* beta  = (const float*)d_in[7];
    float* out = (float*)d_out;

    __nv_bfloat16 *xb, *w1b, *w2b, *h1b, *hbp, *hbT2p;
    float *hp;
    cudaGetSymbolAddress((void**)&xb,    g_xb);
    cudaGetSymbolAddress((void**)&w1b,   g_w1b);
    cudaGetSymbolAddress((void**)&w2b,   g_w2b);
    cudaGetSymbolAddress((void**)&h1b,   g_h1b);
    cudaGetSymbolAddress((void**)&hp,    g_h);
    cudaGetSymbolAddress((void**)&hbp,   g_hb);
    cudaGetSymbolAddress((void**)&hbT2p, g_hbT2);

    cvt_x_blocked<<<NROWS * IND / 8 / 256, 256>>>(x, xb);
    cvt_w_blocked<IND, HIDD><<<IND * HIDD / 8 / 256, 256>>>(W1, w1b);
    cvt_w_blocked<HIDD, OD><<<HIDD * OD / 8 / 256, 256>>>(W2, w2b);

    cudaFuncSetAttribute(hgemm_bulk_kernel<IND, HIDD, true, false, true, false>,
                         cudaFuncAttributeMaxDynamicSharedMemorySize, GEMM_SMEM);
    hgemm_bulk_kernel<IND, HIDD, true, false, true, false>
        <<<dim3(HIDD / 128, NROWS / 128), 256, GEMM_SMEM>>>(
            xb, w1b, b1, nullptr, h1b);

    cudaFuncSetAttribute(hgemm_bulk_kernel<HIDD, OD, false, true, false, true>,
                         cudaFuncAttributeMaxDynamicSharedMemorySize, GEMM_SMEM);
    hgemm_bulk_kernel<HIDD, OD, false, true, false, true>
        <<<dim3(OD / 128, NROWS / 128), 256, GEMM_SMEM>>>(
            h1b, w2b, b2, hp, hbp);

    transpose_half_kernel<<<NB, 256>>>(hp, hbT2p);

    cudaFuncSetAttribute(flash_hmma_kernel,
                         cudaFuncAttributeMaxDynamicSharedMemorySize, FLASH_SMEM);
    flash_hmma_kernel<<<NROWS / 128, 256, FLASH_SMEM>>>(hbp, hbT2p, hp,
                                                        alpha, beta, out);
}

// round 17
// speedup vs baseline: 1.1474x; 1.1474x over previous
#include <cuda_runtime.h>
#include <cuda_bf16.h>
#include <cstdint>
#include <math.h>

// Problem dims (fixed per reference)
#define NROWS 16384
#define IND   512
#define HIDD  256
#define OD    128
#define NB    (NROWS / 128)

// Blocked XOR-swizzled tile formats (validated R10/R14):
//  A-style block: 128 rows x 128 bytes; B-style block: 64 rows x 256 bytes
//  off = r*ROWB + (((b>>4) ^ (r&7))<<4) + (b&15)

// Scratch (device globals; no allocations allowed)
__device__ __nv_bfloat16 g_xb [NROWS * IND];    // x blocked A-blocks
__device__ __nv_bfloat16 g_w1b[IND * HIDD];     // W1 blocked B-blocks
__device__ __nv_bfloat16 g_w2b[HIDD * OD];      // W2 blocked B-blocks
__device__ __nv_bfloat16 g_h1b[NROWS * HIDD];   // h1 blocked A-blocks
__device__ float         g_h  [NROWS * OD];     // fp32 h (epilogue)
// bf16 h swizzled: 128 blocks of 32KB (256B rows)
__device__ __nv_bfloat16 g_hb [NROWS * OD];

// ===========================================================================
// PTX helpers
// ===========================================================================
__device__ __forceinline__ uint32_t smem_to_u32(const void* p) {
    uint32_t a;
    asm("{ .reg .u64 t; cvta.to.shared.u64 t, %1; cvt.u32.u64 %0, t; }"
        : "=r"(a) : "l"(p));
    return a;
}

__device__ __forceinline__ void bulk_cp(uint32_t dst, const void* src,
                                        uint32_t bytes, uint32_t mbar) {
    asm volatile(
        "cp.async.bulk.shared::cluster.global.mbarrier::complete_tx::bytes "
        "[%0], [%1], %2, [%3];"
        :: "r"(dst), "l"(src), "r"(bytes), "r"(mbar) : "memory");
}

#define MBARRIER_INIT(mbar, cnt) \
    asm volatile("mbarrier.init.shared.b64 [%0], %1;" \
        :: "r"((uint32_t)(mbar)), "r"((uint32_t)(cnt)) : "memory")
#define MBARRIER_EXPECT_TX(mbar, tx) \
    asm volatile("mbarrier.arrive.expect_tx.shared.b64 _, [%0], %1;" \
        :: "r"((uint32_t)(mbar)), "r"((uint32_t)(tx)) : "memory")
#define MBARRIER_WAIT_PARITY(mbar, parity) do {                                   \
    uint32_t _m = (uint32_t)(mbar);                                               \
    uint32_t _p = (uint32_t)(parity);                                             \
    uint32_t _done;                                                               \
    asm volatile(                                                                 \
        "{\n\t.reg .pred p;\n\t"                                                  \
        "mbarrier.try_wait.parity.acquire.cta.shared::cta.b64 p, [%1], %2;\n\t"   \
        "selp.b32 %0, 1, 0, p;\n\t}"                                              \
        : "=r"(_done) : "r"(_m), "r"(_p) : "memory");                             \
    if (!_done) {                                                                 \
        asm volatile(                                                             \
            "{\n\t.reg .pred P1;\n\t"                                             \
            "WAIT_LOOP_%=:\n\t"                                                   \
            "mbarrier.try_wait.parity.acquire.cta.shared::cta.b64 P1, [%0], %1, 0x989680;\n\t" \
            "@P1 bra.uni WAIT_DONE_%=;\n\t"                                       \
            "bra.uni WAIT_LOOP_%=;\n\t"                                           \
            "WAIT_DONE_%=:\n\t}"                                                  \
            :: "r"(_m), "r"(_p) : "memory");                                      \
    }                                                                             \
} while (0)

__device__ __forceinline__ void ldsm_x4(uint32_t* r, uint32_t addr) {
    asm volatile("ldmatrix.sync.aligned.m8n8.x4.shared.b16 {%0,%1,%2,%3}, [%4];"
                 : "=r"(r[0]), "=r"(r[1]), "=r"(r[2]), "=r"(r[3]) : "r"(addr));
}
__device__ __forceinline__ void ldsm_x4_t(uint32_t* r, uint32_t addr) {
    asm volatile("ldmatrix.sync.aligned.m8n8.x4.trans.shared.b16 {%0,%1,%2,%3}, [%4];"
                 : "=r"(r[0]), "=r"(r[1]), "=r"(r[2]), "=r"(r[3]) : "r"(addr));
}
__device__ __forceinline__ uint32_t movm(uint32_t a) {
    uint32_t d;
    asm("movmatrix.sync.aligned.m8n8.trans.b16 %0, %1;" : "=r"(d) : "r"(a));
    return d;
}

__device__ __forceinline__ void mma16816(float* c, const uint32_t* a,
                                         const uint32_t b0, const uint32_t b1) {
    asm volatile(
        "mma.sync.aligned.m16n8k16.row.col.f32.bf16.bf16.f32 "
        "{%0,%1,%2,%3}, {%4,%5,%6,%7}, {%8,%9}, {%0,%1,%2,%3};"
        : "+f"(c[0]), "+f"(c[1]), "+f"(c[2]), "+f"(c[3])
        : "r"(a[0]), "r"(a[1]), "r"(a[2]), "r"(a[3]), "r"(b0), "r"(b1));
}

__device__ __forceinline__ uint32_t pack_bf16x2(float hi, float lo) {
    uint32_t d;
    asm("cvt.rn.bf16x2.f32 %0, %1, %2;" : "=r"(d) : "f"(hi), "f"(lo));
    return d;
}
__device__ __forceinline__ uint32_t hmul2(uint32_t a, uint32_t b) {
    uint32_t d;
    asm("mul.rn.bf16x2 %0, %1, %2;" : "=r"(d) : "r"(a), "r"(b));
    return d;
}
__device__ __forceinline__ float ex2f(float x) {
    float d;
    asm("ex2.approx.f32 %0, %1;" : "=f"(d) : "f"(x));
    return d;
}
#define L2E_BF16X2 0x3FB93FB9u   // bf16x2 {log2(e), log2(e)}

// ===========================================================================
// Conversions into blocked swizzled layouts (unchanged)
// ===========================================================================
__global__ __launch_bounds__(256) void cvt_x_blocked(
    const float* __restrict__ x, __nv_bfloat16* __restrict__ xb)
{
    int idx = blockIdx.x * 256 + threadIdx.x;
    int r = idx >> 6;
    int cc = idx & 63;
    const float4* src = (const float4*)(x + (size_t)r * IND + cc * 8);
    float4 v0 = src[0], v1 = src[1];
    uint4 o = make_uint4(pack_bf16x2(v0.y, v0.x), pack_bf16x2(v0.w, v0.z),
                         pack_bf16x2(v1.y, v1.x), pack_bf16x2(v1.w, v1.z));
    uint32_t blk = (uint32_t)((r >> 7) * 8 + (cc >> 3));
    uint32_t off = blk * 16384u + (uint32_t)(r & 127) * 128u
                 + (uint32_t)((((cc & 7) ^ (r & 7)) << 4));
    *(uint4*)((char*)xb + off) = o;
}

template<int K, int NCOLS>
__global__ __launch_bounds__(256) void cvt_w_blocked(
    const float* __restrict__ w, __nv_bfloat16* __restrict__ wb)
{
    int idx = blockIdx.x * 256 + threadIdx.x;
    int cpr = NCOLS / 8;
    int k = idx / cpr;
    int cc = idx % cpr;
    int n0 = cc * 8;
    const float4* src = (const float4*)(w + (size_t)k * NCOLS + n0);
    float4 v0 = src[0], v1 = src[1];
    uint4 o = make_uint4(pack_bf16x2(v0.y, v0.x), pack_bf16x2(v0.w, v0.z),
                         pack_bf16x2(v1.y, v1.x), pack_bf16x2(v1.w, v1.z));
    uint32_t blk = (uint32_t)((k >> 6) * (NCOLS / 128) + (n0 >> 7));
    uint32_t ch  = (uint32_t)((n0 & 127) >> 3);
    uint32_t off = blk * 16384u + (uint32_t)(k & 63) * 256u
                 + ((ch ^ (uint32_t)(k & 7)) << 4);
    *(uint4*)((char*)wb + off) = o;
}

// ===========================================================================
// bf16 HMMA GEMM with bulk-copied blocked operands (R15, frozen)
// ===========================================================================
#define GT_A 16384
#define GT_B 16384
#define GT_STG (GT_A + GT_B)
#define GEMM_SMEM (3 * GT_STG + 64)

template<int KDIM, int NGLOB, bool LEAKY, bool WRITE_F32, bool H1B_OUT, bool SWZ_CB>
__global__ __launch_bounds__(256, 2) void hgemm_bulk_kernel(
    const __nv_bfloat16* __restrict__ A, const __nv_bfloat16* __restrict__ B,
    const float* __restrict__ bias, float* __restrict__ C,
    __nv_bfloat16* __restrict__ Cb)
{
    extern __shared__ char smem[];
    const uint32_t sb = smem_to_u32(smem);
    const uint32_t mb = sb + 3 * GT_STG;
    const int tid = threadIdx.x;
    const int wid = tid >> 5, lane = tid & 31;
    const int m0 = blockIdx.y * 128, n0 = blockIdx.x * 128;
    const char* Abase = (const char*)A;
    const char* Bbase = (const char*)B;
    constexpr int NC = KDIM / 64;

    if (tid == 0) {
        MBARRIER_INIT(mb, 1);
        MBARRIER_INIT(mb + 8, 1);
        MBARRIER_INIT(mb + 16, 1);
    }
    __syncthreads();

    auto kick = [&](int stg, int ck) {
        const uint32_t m_ = mb + 8u * (uint32_t)stg;
        const uint32_t d_ = sb + (uint32_t)stg * GT_STG;
        MBARRIER_EXPECT_TX(m_, GT_STG);
        bulk_cp(d_, Abase + ((size_t)(m0 >> 7) * NC + ck) * 16384, GT_A, m_);
        bulk_cp(d_ + GT_A,
                Bbase + ((size_t)ck * (NGLOB / 128) + (n0 >> 7)) * 16384,
                GT_B, m_);
    };
    if (tid == 0) {
        kick(0, 0);
        if (NC > 1) kick(1, 1);
        if (NC > 2) kick(2, 2);
    }

    float acc[16][4];
    #pragma unroll
    for (int i = 0; i < 16; i++)
        #pragma unroll
        for (int j = 0; j < 4; j++) acc[i][j] = 0.f;

    const int brow = lane & 15;
    const int hc = lane >> 4;
    const int xr = lane & 7;
    const int vrow = ((lane >> 4) << 3) + (lane & 7);
    const int vhc = (lane >> 3) & 1;

    int st = 0, ph = 0;
    for (int ck = 0; ck < NC; ck++) {
        MBARRIER_WAIT_PARITY(mb + 8u * (uint32_t)st, ph);

        const uint32_t cA = sb + (uint32_t)st * GT_STG;
        const uint32_t cB = cA + GT_A;

        uint32_t af[4][4];
        const uint32_t ab = cA + (uint32_t)(wid * 16 + brow) * 128u;
        #pragma unroll
        for (int kt = 0; kt < 4; kt++)
            ldsm_x4(af[kt], ab + (uint32_t)(((kt * 2 + hc) ^ xr) << 4));

        #pragma unroll
        for (int kt = 0; kt < 4; kt++) {
            const uint32_t rbrow = cB + (uint32_t)(kt * 16 + vrow) * 256u;
            #pragma unroll
            for (int jp = 0; jp < 8; jp++) {
                uint32_t r[4];
                ldsm_x4_t(r, rbrow + (uint32_t)(((jp * 2 + vhc) ^ xr) << 4));
                mma16816(acc[2 * jp],     af[kt], r[0], r[2]);
                mma16816(acc[2 * jp + 1], af[kt], r[1], r[3]);
            }
        }

        if (ck + 3 < NC) {
            __syncthreads();
            if (tid == 0) kick(st, ck + 3);
        }

        if (++st == 3) { st = 0; ph ^= 1; }
    }

    const int g = lane >> 2, t = lane & 3;
    const int row_lo = m0 + wid * 16 + g;
    const int row_hi = row_lo + 8;
    #pragma unroll
    for (int nt = 0; nt < 16; nt++) {
        const int col = n0 + nt * 8 + 2 * t;
        const float bb0 = bias[col], bb1 = bias[col + 1];
        float v0 = acc[nt][0] + bb0, v1 = acc[nt][1] + bb1;
        float v2 = acc[nt][2] + bb0, v3 = acc[nt][3] + bb1;
        if (LEAKY) {
            v0 = v0 >= 0.f ? v0 : 0.01f * v0;
            v1 = v1 >= 0.f ? v1 : 0.01f * v1;
            v2 = v2 >= 0.f ? v2 : 0.01f * v2;
            v3 = v3 >= 0.f ? v3 : 0.01f * v3;
        }
        if (WRITE_F32) {
            *(float2*)(C + (size_t)row_lo * NGLOB + col) = make_float2(v0, v1);
            *(float2*)(C + (size_t)row_hi * NGLOB + col) = make_float2(v2, v3);
        }
        if (H1B_OUT) {
            const uint32_t ck2 = (uint32_t)(col >> 6);
            const uint32_t ch  = (uint32_t)((col & 63) >> 3);
            const uint32_t inb = (uint32_t)((col * 2) & 15);
            const uint32_t b_lo = ((uint32_t)(row_lo >> 7) * (NGLOB / 64) + ck2) * 16384u
                + (uint32_t)(row_lo & 127) * 128u
                + (((ch ^ (uint32_t)(row_lo & 7)) << 4) | inb);
            const uint32_t b_hi = ((uint32_t)(row_hi >> 7) * (NGLOB / 64) + ck2) * 16384u
                + (uint32_t)(row_hi & 127) * 128u
                + (((ch ^ (uint32_t)(row_hi & 7)) << 4) | inb);
            *(uint32_t*)((char*)Cb + b_lo) = pack_bf16x2(v1, v0);
            *(uint32_t*)((char*)Cb + b_hi) = pack_bf16x2(v3, v2);
        }
        if (SWZ_CB) {
            const uint32_t chunk = (uint32_t)(col >> 3);
            const uint32_t inb   = (uint32_t)((col * 2) & 15);
            const uint32_t off_lo = ((uint32_t)(row_lo >> 7)) * 32768u
                + (uint32_t)(row_lo & 127) * 256u
                + (((chunk ^ (uint32_t)(row_lo & 7)) << 4) | inb);
            const uint32_t off_hi = ((uint32_t)(row_hi >> 7)) * 32768u
                + (uint32_t)(row_hi & 127) * 256u
                + (((chunk ^ (uint32_t)(row_hi & 7)) << 4) | inb);
            *(uint32_t*)((char*)Cb + off_lo) = pack_bf16x2(v1, v0);
            *(uint32_t*)((char*)Cb + off_hi) = pack_bf16x2(v3, v2);
        }
    }
}

// ===========================================================================
// HMMA flash similarity kernel — R17: R15 inner loop VERBATIM, but 64 Q-rows
// per CTA / 128 threads / 2 CTAs per SM: two independent CTAs interleave
// their exp/pack/sync phases on each SM, keeping the tensor pipe fed.
// (Retest of R8's theory with the LDGSTS confound removed by bulk copies.)
// ===========================================================================
#define TILE_B 32768
#define FLASH_SMEM (3 * TILE_B + 64)   // 98368; x2 CTAs = 196736 <= 228KB/SM

__global__ __launch_bounds__(128, 2)
void flash_hmma_kernel(const __nv_bfloat16* __restrict__ hbs,  // swizzled
                       const float* __restrict__ h,
                       const float* __restrict__ alpha,
                       const float* __restrict__ beta,
                       float* __restrict__ out)
{
    extern __shared__ char smem[];
    const uint32_t sbase = smem_to_u32(smem);
    const uint32_t mQ = sbase + 3 * TILE_B;   // key-stage mb[s] at mQ+8+8s
    const int tid = threadIdx.x;
    const int wid = tid >> 5, lane = tid & 31;   // 4 warps, 16 rows each
    const int r0 = blockIdx.x * 64;
    const char* hbase = (const char*)hbs;

    if (tid == 0) {
        MBARRIER_INIT(mQ, 1);
        MBARRIER_INIT(mQ + 8, 1);
        MBARRIER_INIT(mQ + 16, 1);
        MBARRIER_INIT(mQ + 24, 1);
    }
    __syncthreads();

    // Q tile: 64 rows = 16KB, contiguous in the blocked layout at r0*256
    if (tid == 0) {
        MBARRIER_EXPECT_TX(mQ, 16384);
        bulk_cp(sbase, hbase + (size_t)blockIdx.x * 16384, 16384, mQ);
    }

    const int brow = lane & 15;
    const int hc = lane >> 4;
    const int xr = lane & 7;
    uint32_t choff[8];
    #pragma unroll
    for (int dk = 0; dk < 8; dk++)
        choff[dk] = (uint32_t)(((dk * 2 + hc) ^ xr) << 4);

    MBARRIER_WAIT_PARITY(mQ, 0);

    uint32_t qf[8][4];
    {
        const uint32_t qb = sbase + (uint32_t)(wid * 16 + brow) * 256u;
        #pragma unroll
        for (int kt = 0; kt < 8; kt++) {
            ldsm_x4(qf[kt], qb + choff[kt]);
            #pragma unroll
            for (int i = 0; i < 4; i++)
                qf[kt][i] = hmul2(qf[kt][i], L2E_BF16X2);  // fold log2(e)
        }
    }
    __syncthreads();   // all threads done reading Q from stage0

    // Kick key-blocks 0..1 into stages 0..1
    if (tid == 0) {
        MBARRIER_EXPECT_TX(mQ + 8, TILE_B);
        bulk_cp(sbase, hbase, TILE_B, mQ + 8);
        MBARRIER_EXPECT_TX(mQ + 16, TILE_B);
        bulk_cp(sbase + TILE_B, hbase + TILE_B, TILE_B, mQ + 16);
    }

    float oacc[16][4];
    #pragma unroll
    for (int i = 0; i < 16; i++)
        #pragma unroll
        for (int j = 0; j < 4; j++) oacc[i][j] = 0.f;
    float l0 = 0.f, l1 = 0.f;

    int st = 0, ph = 0;
    for (int kb = 0; kb < NB; kb++) {
        MBARRIER_WAIT_PARITY(mQ + 8 + 8 * (uint32_t)st, ph);
        __syncthreads();   // iter kb-1 done -> stage (st+2)%3 is free
        if (tid == 0 && kb + 2 < NB) {
            int pst = st + 2; if (pst >= 3) pst -= 3;
            const uint32_t mm = mQ + 8 + 8 * (uint32_t)pst;
            MBARRIER_EXPECT_TX(mm, TILE_B);
            bulk_cp(sbase + (uint32_t)pst * TILE_B,
                    hbase + (size_t)(kb + 2) * TILE_B, TILE_B, mm);
        }

        const uint32_t cur = sbase + (uint32_t)st * TILE_B;

        #pragma unroll
        for (int nbk = 0; nbk < 8; nbk++) {
            uint32_t r[8][4];
            const uint32_t rb = cur + (uint32_t)(nbk * 16 + brow) * 256u;
            #pragma unroll
            for (int dk = 0; dk < 8; dk++) ldsm_x4(r[dk], rb + choff[dk]);

            float s0[4] = {0.f, 0.f, 0.f, 0.f};
            float s1[4] = {0.f, 0.f, 0.f, 0.f};
            #pragma unroll
            for (int dk = 0; dk < 8; dk++) {
                mma16816(s0, qf[dk], r[dk][0], r[dk][2]);
                mma16816(s1, qf[dk], r[dk][1], r[dk][3]);
            }

            float p00 = s0[0] > 0.f ? ex2f(s0[0]) : 0.f;
            float p01 = s0[1] > 0.f ? ex2f(s0[1]) : 0.f;
            float p02 = s0[2] > 0.f ? ex2f(s0[2]) : 0.f;
            float p03 = s0[3] > 0.f ? ex2f(s0[3]) : 0.f;
            float p10 = s1[0] > 0.f ? ex2f(s1[0]) : 0.f;
            float p11 = s1[1] > 0.f ? ex2f(s1[1]) : 0.f;
            float p12 = s1[2] > 0.f ? ex2f(s1[2]) : 0.f;
            float p13 = s1[3] > 0.f ? ex2f(s1[3]) : 0.f;
            l0 += (p00 + p01) + (p10 + p11);
            l1 += (p02 + p03) + (p12 + p13);
            uint32_t af[4] = { pack_bf16x2(p01, p00), pack_bf16x2(p03, p02),
                               pack_bf16x2(p11, p10), pack_bf16x2(p13, p12) };

            #pragma unroll
            for (int dk = 0; dk < 8; dk++) {
                mma16816(oacc[2 * dk],     af, movm(r[dk][0]), movm(r[dk][1]));
                mma16816(oacc[2 * dk + 1], af, movm(r[dk][2]), movm(r[dk][3]));
            }
        }

        if (++st == 3) { st = 0; ph ^= 1; }
    }

    l0 += __shfl_xor_sync(0xffffffffu, l0, 1);
    l0 += __shfl_xor_sync(0xffffffffu, l0, 2);
    l1 += __shfl_xor_sync(0xffffffffu, l1, 1);
    l1 += __shfl_xor_sync(0xffffffffu, l1, 2);

    const float a_ = alpha[0], b_ = beta[0];
    const float s0_ = a_ / l0, s1_ = a_ / l1;
    const int g = lane >> 2, t = lane & 3;
    const int row_lo = r0 + wid * 16 + g;
    const int row_hi = row_lo + 8;

    float mx0 = -INFINITY, mx1 = -INFINITY;
    #pragma unroll
    for (int nt = 0; nt < 16; nt++) {
        const int col = nt * 8 + 2 * t;
        float2 hlo = *(const float2*)(h + (size_t)row_lo * OD + col);
        float2 hhi = *(const float2*)(h + (size_t)row_hi * OD + col);
        float v0 = s0_ * oacc[nt][0] + b_ * hlo.x;
        float v1 = s0_ * oacc[nt][1] + b_ * hlo.y;
        float v2 = s1_ * oacc[nt][2] + b_ * hhi.x;
        float v3 = s1_ * oacc[nt][3] + b_ * hhi.y;
        oacc[nt][0] = v0; oacc[nt][1] = v1;
        oacc[nt][2] = v2; oacc[nt][3] = v3;
        mx0 = fmaxf(mx0, fmaxf(v0, v1));
        mx1 = fmaxf(mx1, fmaxf(v2, v3));
    }
    mx0 = fmaxf(mx0, __shfl_xor_sync(0xffffffffu, mx0, 1));
    mx0 = fmaxf(mx0, __shfl_xor_sync(0xffffffffu, mx0, 2));
    mx1 = fmaxf(mx1, __shfl_xor_sync(0xffffffffu, mx1, 1));
    mx1 = fmaxf(mx1, __shfl_xor_sync(0xffffffffu, mx1, 2));

    float se0 = 0.f, se1 = 0.f;
    #pragma unroll
    for (int nt = 0; nt < 16; nt++) {
        se0 += __expf(oacc[nt][0] - mx0) + __expf(oacc[nt][1] - mx0);
        se1 += __expf(oacc[nt][2] - mx1) + __expf(oacc[nt][3] - mx1);
    }
    se0 += __shfl_xor_sync(0xffffffffu, se0, 1);
    se0 += __shfl_xor_sync(0xffffffffu, se0, 2);
    se1 += __shfl_xor_sync(0xffffffffu, se1, 1);
    se1 += __shfl_xor_sync(0xffffffffu, se1, 2);
    const float lse0 = mx0 + logf(se0);
    const float lse1 = mx1 + logf(se1);

    #pragma unroll
    for (int nt = 0; nt < 16; nt++) {
        const int col = nt * 8 + 2 * t;
        *(float2*)(out + (size_t)row_lo * OD + col) =
            make_float2(oacc[nt][0] - lse0, oacc[nt][1] - lse0);
        *(float2*)(out + (size_t)row_hi * OD + col) =
            make_float2(oacc[nt][2] - lse1, oacc[nt][3] - lse1);
    }
}

// ===========================================================================
// Launch. Inputs: 0:x 1:g 2:W1 3:b1 4:W2 5:b2 6:alpha 7:beta
// ===========================================================================
extern "C" void kernel_launch(void* const* d_in, const int* in_sizes, int n_in,
                              void* d_out, int out_size)
{
    (void)in_sizes; (void)n_in; (void)out_size;
    const float* x     = (const float*)d_in[0];
    const float* W1    = (const float*)d_in[2];
    const float* b1    = (const float*)d_in[3];
    const float* W2    = (const float*)d_in[4];
    const float* b2    = (const float*)d_in[5];
    const float* alpha = (const float*)d_in[6];
    const float* beta  = (const float*)d_in[7];
    float* out = (float*)d_out;

    __nv_bfloat16 *xb, *w1b, *w2b, *h1b, *hbp;
    float *hp;
    cudaGetSymbolAddress((void**)&xb,  g_xb);
    cudaGetSymbolAddress((void**)&w1b, g_w1b);
    cudaGetSymbolAddress((void**)&w2b, g_w2b);
    cudaGetSymbolAddress((void**)&h1b, g_h1b);
    cudaGetSymbolAddress((void**)&hp,  g_h);
    cudaGetSymbolAddress((void**)&hbp, g_hb);

    cvt_x_blocked<<<NROWS * IND / 8 / 256, 256>>>(x, xb);
    cvt_w_blocked<IND, HIDD><<<IND * HIDD / 8 / 256, 256>>>(W1, w1b);
    cvt_w_blocked<HIDD, OD><<<HIDD * OD / 8 / 256, 256>>>(W2, w2b);

    cudaFuncSetAttribute(hgemm_bulk_kernel<IND, HIDD, true, false, true, false>,
                         cudaFuncAttributeMaxDynamicSharedMemorySize, GEMM_SMEM);
    hgemm_bulk_kernel<IND, HIDD, true, false, true, false>
        <<<dim3(HIDD / 128, NROWS / 128), 256, GEMM_SMEM>>>(
            xb, w1b, b1, nullptr, h1b);

    cudaFuncSetAttribute(hgemm_bulk_kernel<HIDD, OD, false, true, false, true>,
                         cudaFuncAttributeMaxDynamicSharedMemorySize, GEMM_SMEM);
    hgemm_bulk_kernel<HIDD, OD, false, true, false, true>
        <<<dim3(OD / 128, NROWS / 128), 256, GEMM_SMEM>>>(
            h1b, w2b, b2, hp, hbp);

    cudaFuncSetAttribute(flash_hmma_kernel,
                         cudaFuncAttributeMaxDynamicSharedMemorySize, FLASH_SMEM);
    flash_hmma_kernel<<<NROWS / 64, 128, FLASH_SMEM>>>(hbp, hp, alpha, beta, out);
}